// round 3
// baseline (speedup 1.0000x reference)
#include <cuda_runtime.h>
#include <math.h>

// Problem constants
#define BATCH 32
#define SEQ   512
#define DM    1024
#define NH    16
#define DK    64
#define MTOT  (BATCH * SEQ)   // 16384

// Scratch (device globals; no runtime allocation allowed)
__device__ float g_q[MTOT * DM];
__device__ float g_k[MTOT * DM];
__device__ float g_v[MTOT * DM];
__device__ float g_attn[MTOT * DM];
__device__ float g_kv[BATCH * NH * DK * DK];
__device__ float g_ksum[BATCH * NH * DK];

// ---------------------------------------------------------------------------
// SGEMM + bias (+ optional phi = elu(x)+1), C[M,N] = A[M,K] @ W[K,N] + b
// 128x128x8 tile, 256 threads, 8x8 per-thread register tile.
// Double-buffered smem: next tile's global loads are issued before compute,
// stored to the alternate buffer after compute; one barrier per k-step.
// ---------------------------------------------------------------------------
template <int ACT>
__global__ __launch_bounds__(256) void sgemm_bias(
    const float* __restrict__ A, const float* __restrict__ W,
    const float* __restrict__ bias, float* __restrict__ C,
    int M, int N, int K)
{
    __shared__ float As[2][8][128];
    __shared__ float Bs[2][8][128];

    const int tid = threadIdx.x;
    const int bm  = blockIdx.y;
    const int bn  = blockIdx.x;

    // A tile load mapping: 128 rows x 8 cols, one float4 per thread
    const int aRow = tid >> 1;
    const int aCol = (tid & 1) * 4;
    // B tile load mapping: 8 rows x 128 cols, one float4 per thread
    const int bRow = tid >> 5;
    const int bCol = (tid & 31) * 4;

    const float* Ab = A + (size_t)(bm * 128) * K;
    const float* Wb = W + bn * 128;

    const int tr = tid >> 4;   // 0..15
    const int tc = tid & 15;   // 0..15

    float acc[8][8];
#pragma unroll
    for (int i = 0; i < 8; i++)
#pragma unroll
        for (int j = 0; j < 8; j++) acc[i][j] = 0.f;

    const int NT = K / 8;

    // Preload tile 0 into buffer 0
    {
        float4 av = *(const float4*)(Ab + (size_t)aRow * K + aCol);
        As[0][aCol + 0][aRow] = av.x;
        As[0][aCol + 1][aRow] = av.y;
        As[0][aCol + 2][aRow] = av.z;
        As[0][aCol + 3][aRow] = av.w;
        float4 bv = *(const float4*)(Wb + (size_t)bRow * N + bCol);
        *(float4*)&Bs[0][bRow][bCol] = bv;
    }
    __syncthreads();

    for (int t = 0; t < NT; t++) {
        const int cur = t & 1;
        const int nxt = cur ^ 1;

        float4 av, bv;
        const bool more = (t + 1 < NT);
        if (more) {
            const int k0 = (t + 1) * 8;
            av = *(const float4*)(Ab + (size_t)aRow * K + k0 + aCol);
            bv = *(const float4*)(Wb + (size_t)(k0 + bRow) * N + bCol);
        }

#pragma unroll
        for (int kk = 0; kk < 8; kk++) {
            float a[8], b[8];
            *(float4*)(a)     = *(float4*)&As[cur][kk][tr * 8];
            *(float4*)(a + 4) = *(float4*)&As[cur][kk][tr * 8 + 4];
            *(float4*)(b)     = *(float4*)&Bs[cur][kk][tc * 8];
            *(float4*)(b + 4) = *(float4*)&Bs[cur][kk][tc * 8 + 4];
#pragma unroll
            for (int i = 0; i < 8; i++)
#pragma unroll
                for (int j = 0; j < 8; j++)
                    acc[i][j] = fmaf(a[i], b[j], acc[i][j]);
        }

        if (more) {
            As[nxt][aCol + 0][aRow] = av.x;
            As[nxt][aCol + 1][aRow] = av.y;
            As[nxt][aCol + 2][aRow] = av.z;
            As[nxt][aCol + 3][aRow] = av.w;
            *(float4*)&Bs[nxt][bRow][bCol] = bv;
        }
        __syncthreads();
    }

    // Epilogue
    const int crow = bm * 128 + tr * 8;
    const int ccol = bn * 128 + tc * 8;
    float bc[8];
    *(float4*)(bc)     = *(const float4*)(bias + ccol);
    *(float4*)(bc + 4) = *(const float4*)(bias + ccol + 4);

#pragma unroll
    for (int i = 0; i < 8; i++) {
        float row[8];
#pragma unroll
        for (int j = 0; j < 8; j++) {
            float v = acc[i][j] + bc[j];
            if (ACT) {
                // phi(x) = elu(x) + 1 : x>0 ? x+1 : exp(x)
                v = (v > 0.f) ? (v + 1.f) : expf(v);
            }
            row[j] = v;
        }
        *(float4*)(C + (size_t)(crow + i) * N + ccol)     = *(float4*)(row);
        *(float4*)(C + (size_t)(crow + i) * N + ccol + 4) = *(float4*)(row + 4);
    }
}

// ---------------------------------------------------------------------------
// KV state: per (b,h): kv[d][e] = sum_n kf[n,d] * v[n,e]; ksum[d] = sum_n kf[n,d]
// Grid: 512 blocks (b*16+h), 256 threads; 4x4 register tile per thread.
// ---------------------------------------------------------------------------
__global__ __launch_bounds__(256) void kv_state_kernel(
    const float* __restrict__ Kf, const float* __restrict__ V)
{
    const int bh = blockIdx.x;
    const int b = bh >> 4;
    const int h = bh & 15;

    __shared__ float ks[64][64];
    __shared__ float vs[64][64];

    const int tid = threadIdx.x;
    const int d0 = (tid >> 4) * 4;
    const int e0 = (tid & 15) * 4;

    const int lrow = tid >> 2;          // 0..63
    const int lc0  = (tid & 3) * 16;    // 0,16,32,48

    const float* kb = Kf + (size_t)(b * SEQ) * DM + h * DK;
    const float* vb = V  + (size_t)(b * SEQ) * DM + h * DK;

    float acc[4][4];
#pragma unroll
    for (int i = 0; i < 4; i++)
#pragma unroll
        for (int j = 0; j < 4; j++) acc[i][j] = 0.f;
    float ksacc = 0.f;

    for (int c = 0; c < SEQ; c += 64) {
        const float* kr = kb + (size_t)(c + lrow) * DM;
        const float* vr = vb + (size_t)(c + lrow) * DM;
#pragma unroll
        for (int j = 0; j < 4; j++) {
            *(float4*)&ks[lrow][lc0 + j * 4] = *(const float4*)(kr + lc0 + j * 4);
            *(float4*)&vs[lrow][lc0 + j * 4] = *(const float4*)(vr + lc0 + j * 4);
        }
        __syncthreads();

#pragma unroll 8
        for (int n = 0; n < 64; n++) {
            float a[4], bb[4];
            *(float4*)a  = *(float4*)&ks[n][d0];
            *(float4*)bb = *(float4*)&vs[n][e0];
#pragma unroll
            for (int i = 0; i < 4; i++)
#pragma unroll
                for (int j = 0; j < 4; j++)
                    acc[i][j] = fmaf(a[i], bb[j], acc[i][j]);
        }

        if (tid < 64) {
#pragma unroll 8
            for (int n = 0; n < 64; n++) ksacc += ks[n][tid];
        }
        __syncthreads();
    }

    float* kvout = g_kv + (size_t)bh * DK * DK;
#pragma unroll
    for (int i = 0; i < 4; i++)
        *(float4*)(kvout + (size_t)(d0 + i) * DK + e0) = *(float4*)acc[i];

    if (tid < 64) g_ksum[bh * DK + tid] = ksacc;
}

// ---------------------------------------------------------------------------
// Attention out: per (b,h): out[n,e] = (qf[n,:] . kv[:,e]) / (qf[n,:] . ksum + eps)
// Grid: 512 blocks, 256 threads; n-chunks of 64; 4x4 register tile.
// ---------------------------------------------------------------------------
__global__ __launch_bounds__(256) void attn_out_kernel(const float* __restrict__ Qf)
{
    const int bh = blockIdx.x;
    const int b = bh >> 4;
    const int h = bh & 15;

    __shared__ float kvs[64][64];
    __shared__ float ksum_s[64];
    __shared__ float qs[64][65];    // padded: conflict-free column access
    __shared__ float denom[64];

    const int tid = threadIdx.x;
    const int lrow = tid >> 2;
    const int lc0  = (tid & 3) * 16;

    // load kv state + ksum
    {
        const float* kvb = g_kv + (size_t)bh * DK * DK;
#pragma unroll
        for (int j = 0; j < 4; j++)
            *(float4*)&kvs[lrow][lc0 + j * 4] = *(const float4*)(kvb + (size_t)lrow * DK + lc0 + j * 4);
        if (tid < 64) ksum_s[tid] = g_ksum[bh * DK + tid];
    }
    __syncthreads();

    const float* qb = Qf     + (size_t)(b * SEQ) * DM + h * DK;
    float*       ob = g_attn + (size_t)(b * SEQ) * DM + h * DK;

    const int n0 = (tid >> 4) * 4;
    const int e0 = (tid & 15) * 4;

    for (int c = 0; c < SEQ; c += 64) {
        const float* qr = qb + (size_t)(c + lrow) * DM;
#pragma unroll
        for (int j = 0; j < 4; j++) {
            float4 t = *(const float4*)(qr + lc0 + j * 4);
            qs[lrow][lc0 + j * 4 + 0] = t.x;
            qs[lrow][lc0 + j * 4 + 1] = t.y;
            qs[lrow][lc0 + j * 4 + 2] = t.z;
            qs[lrow][lc0 + j * 4 + 3] = t.w;
        }
        __syncthreads();

        if (tid < 64) {
            float s = 0.f;
#pragma unroll 8
            for (int d = 0; d < 64; d++) s = fmaf(qs[tid][d], ksum_s[d], s);
            denom[tid] = s + 1e-6f;
        }
        __syncthreads();

        float acc[4][4];
#pragma unroll
        for (int i = 0; i < 4; i++)
#pragma unroll
            for (int j = 0; j < 4; j++) acc[i][j] = 0.f;

#pragma unroll 8
        for (int d = 0; d < 64; d++) {
            float a[4], bb[4];
#pragma unroll
            for (int i = 0; i < 4; i++) a[i] = qs[n0 + i][d];
            *(float4*)bb = *(float4*)&kvs[d][e0];
#pragma unroll
            for (int i = 0; i < 4; i++)
#pragma unroll
                for (int j = 0; j < 4; j++)
                    acc[i][j] = fmaf(a[i], bb[j], acc[i][j]);
        }

#pragma unroll
        for (int i = 0; i < 4; i++) {
            float inv = 1.f / denom[n0 + i];
            float row[4];
#pragma unroll
            for (int j = 0; j < 4; j++) row[j] = acc[i][j] * inv;
            *(float4*)(ob + (size_t)(c + n0 + i) * DM + e0) = *(float4*)row;
        }
        __syncthreads();
    }
}

// ---------------------------------------------------------------------------
extern "C" void kernel_launch(void* const* d_in, const int* in_sizes, int n_in,
                              void* d_out, int out_size)
{
    const float* x  = (const float*)d_in[0];
    const float* Wq = (const float*)d_in[1];
    const float* bq = (const float*)d_in[2];
    const float* Wk = (const float*)d_in[3];
    const float* bk = (const float*)d_in[4];
    const float* Wv = (const float*)d_in[5];
    const float* bv = (const float*)d_in[6];
    const float* Wo = (const float*)d_in[7];
    const float* bo = (const float*)d_in[8];
    float* out = (float*)d_out;

    float *q, *k, *v, *attn;
    cudaGetSymbolAddress((void**)&q,    g_q);
    cudaGetSymbolAddress((void**)&k,    g_k);
    cudaGetSymbolAddress((void**)&v,    g_v);
    cudaGetSymbolAddress((void**)&attn, g_attn);

    dim3 gg(DM / 128, MTOT / 128);   // (8, 128)

    sgemm_bias<1><<<gg, 256>>>(x, Wq, bq, q, MTOT, DM, DM);
    sgemm_bias<1><<<gg, 256>>>(x, Wk, bk, k, MTOT, DM, DM);
    sgemm_bias<0><<<gg, 256>>>(x, Wv, bv, v, MTOT, DM, DM);

    kv_state_kernel<<<BATCH * NH, 256>>>(k, v);
    attn_out_kernel<<<BATCH * NH, 256>>>(q);

    sgemm_bias<0><<<gg, 256>>>(attn, Wo, bo, out, MTOT, DM, DM);
}

// round 8
// speedup vs baseline: 2.1623x; 2.1623x over previous
#include <cuda_runtime.h>
#include <cuda_bf16.h>
#include <math.h>
#include <stdint.h>

// Problem constants
#define BATCH 32
#define SEQ   512
#define DM    1024
#define NH    16
#define DK    64
#define MTOT  (BATCH * SEQ)   // 16384

// fp32 scratch
__device__ float g_q[MTOT * DM];
__device__ float g_k[MTOT * DM];
__device__ float g_v[MTOT * DM];
__device__ float g_attn[MTOT * DM];
__device__ float g_kv[BATCH * NH * DK * DK];
__device__ float g_ksum[BATCH * NH * DK];

// bf16 split scratch (hi/lo decomposition of fp32 operands)
__device__ __nv_bfloat16 g_xh[MTOT * DM];
__device__ __nv_bfloat16 g_xl[MTOT * DM];
__device__ __nv_bfloat16 g_ath[MTOT * DM];
__device__ __nv_bfloat16 g_atl[MTOT * DM];
__device__ __nv_bfloat16 g_wh[4 * DM * DM];
__device__ __nv_bfloat16 g_wl[4 * DM * DM];

// ---------------------------------------------------------------------------
// Split fp32 -> bf16 hi + bf16 lo  (x ~= hi + lo, |x-hi-lo| <~ 2^-16 |x|)
// ---------------------------------------------------------------------------
__global__ void split_kernel(const float* __restrict__ src,
                             __nv_bfloat16* __restrict__ hi,
                             __nv_bfloat16* __restrict__ lo, int n)
{
    int i = (blockIdx.x * blockDim.x + threadIdx.x) * 4;
    if (i >= n) return;
    float4 v = *(const float4*)(src + i);

    __nv_bfloat16 h0 = __float2bfloat16(v.x);
    __nv_bfloat16 h1 = __float2bfloat16(v.y);
    __nv_bfloat16 h2 = __float2bfloat16(v.z);
    __nv_bfloat16 h3 = __float2bfloat16(v.w);
    __nv_bfloat16 l0 = __float2bfloat16(v.x - __bfloat162float(h0));
    __nv_bfloat16 l1 = __float2bfloat16(v.y - __bfloat162float(h1));
    __nv_bfloat16 l2 = __float2bfloat16(v.z - __bfloat162float(h2));
    __nv_bfloat16 l3 = __float2bfloat16(v.w - __bfloat162float(h3));

    __nv_bfloat162 hp0; hp0.x = h0; hp0.y = h1;
    __nv_bfloat162 hp1; hp1.x = h2; hp1.y = h3;
    __nv_bfloat162 lp0; lp0.x = l0; lp0.y = l1;
    __nv_bfloat162 lp1; lp1.x = l2; lp1.y = l3;
    *(__nv_bfloat162*)(hi + i)     = hp0;
    *(__nv_bfloat162*)(hi + i + 2) = hp1;
    *(__nv_bfloat162*)(lo + i)     = lp0;
    *(__nv_bfloat162*)(lo + i + 2) = lp1;
}

// ---------------------------------------------------------------------------
// PTX helpers
// ---------------------------------------------------------------------------
__device__ __forceinline__ uint32_t smem_u32(const void* p)
{
    return (uint32_t)__cvta_generic_to_shared(p);
}
__device__ __forceinline__ void ldsm4(uint32_t* r, uint32_t a)
{
    asm volatile("ldmatrix.sync.aligned.m8n8.x4.shared.b16 {%0,%1,%2,%3}, [%4];"
                 : "=r"(r[0]), "=r"(r[1]), "=r"(r[2]), "=r"(r[3]) : "r"(a));
}
__device__ __forceinline__ void ldsm2t(uint32_t* r, uint32_t a)
{
    asm volatile("ldmatrix.sync.aligned.m8n8.x2.trans.shared.b16 {%0,%1}, [%2];"
                 : "=r"(r[0]), "=r"(r[1]) : "r"(a));
}
__device__ __forceinline__ void mma16816(float* c, const uint32_t* a, const uint32_t* b)
{
    asm volatile(
        "mma.sync.aligned.m16n8k16.row.col.f32.bf16.bf16.f32 "
        "{%0,%1,%2,%3}, {%4,%5,%6,%7}, {%8,%9}, {%0,%1,%2,%3};"
        : "+f"(c[0]), "+f"(c[1]), "+f"(c[2]), "+f"(c[3])
        : "r"(a[0]), "r"(a[1]), "r"(a[2]), "r"(a[3]), "r"(b[0]), "r"(b[1]));
}
#define CPA16(dst, src) \
    asm volatile("cp.async.cg.shared.global [%0], [%1], 16;" :: "r"(dst), "l"(src))
#define CP_COMMIT() asm volatile("cp.async.commit_group;")
#define CP_WAIT1()  asm volatile("cp.async.wait_group 1;")
#define CP_WAIT0()  asm volatile("cp.async.wait_group 0;")

// ---------------------------------------------------------------------------
// Tensor-core GEMM: C[M,N] = (Ah+Al)[M,K] @ (Bh+Bl)[K,N] + bias (+ phi)
// 3-term split-bf16: AhBh + AhBl + AlBh. 128x128 block, BK=16, 256 threads,
// 8 warps (2M x 4N), warp tile 64x32 via m16n8k16. cp.async double buffered.
// A smem rows padded to 24 bf16 (48B) and B rows to 136 bf16 (272B):
// both give distinct 16B banks across the 8 rows of an ldmatrix fetch.
// ---------------------------------------------------------------------------
#define BM 128
#define BN 128
#define BK 16
#define A_PAD 24
#define B_PAD 136

template <int ACT>
__global__ __launch_bounds__(256) void mma_gemm(
    const __nv_bfloat16* __restrict__ Ah, const __nv_bfloat16* __restrict__ Al,
    const __nv_bfloat16* __restrict__ Bh, const __nv_bfloat16* __restrict__ Bl,
    const float* __restrict__ bias, float* __restrict__ C,
    int M, int N, int K)
{
    __shared__ __nv_bfloat16 sA[2][2][BM][A_PAD];   // [buf][hi/lo][row][col]
    __shared__ __nv_bfloat16 sB[2][2][BK][B_PAD];

    const int tid  = threadIdx.x;
    const int lane = tid & 31;
    const int warp = tid >> 5;
    const int warpM = warp & 1;   // 0..1
    const int warpN = warp >> 1;  // 0..3
    const int bm = blockIdx.y;
    const int bn = blockIdx.x;

    // cp.async source mapping (one 16B op per thread per buffer per array)
    const int ar = tid >> 1;            // A row 0..127
    const int ac = (tid & 1) * 8;       // A col chunk (8 bf16 = 16B)
    const int br = tid >> 4;            // B row 0..15
    const int bc = (tid & 15) * 8;      // B col chunk

    const __nv_bfloat16* Agh = Ah + (size_t)(bm * BM + ar) * K + ac;
    const __nv_bfloat16* Agl = Al + (size_t)(bm * BM + ar) * K + ac;
    const __nv_bfloat16* Bgh = Bh + (size_t)br * N + bn * BN + bc;
    const __nv_bfloat16* Bgl = Bl + (size_t)br * N + bn * BN + bc;

    const uint32_t sAbase = smem_u32(sA);
    const uint32_t sBbase = smem_u32(sB);
    const uint32_t A_HL  = BM * A_PAD * 2;       // bytes: one hi or lo plane
    const uint32_t A_BUF = 2 * A_HL;
    const uint32_t B_HL  = BK * B_PAD * 2;
    const uint32_t B_BUF = 2 * B_HL;

    const uint32_t dAh = sAbase + (ar * A_PAD + ac) * 2;
    const uint32_t dAl = dAh + A_HL;
    const uint32_t dBh = sBbase + (br * B_PAD + bc) * 2;
    const uint32_t dBl = dBh + B_HL;

    // ldmatrix address bases
    const int arow = warpM * 64 + (lane & 15);
    const int acol = (lane >> 4) * 8;
    const uint32_t aAddr0 = sAbase + (arow * A_PAD + acol) * 2;
    const int brow = lane & 15;
    const uint32_t bAddr0 = sBbase + (brow * B_PAD + warpN * 32) * 2;

    float c[4][4][4];
#pragma unroll
    for (int mi = 0; mi < 4; mi++)
#pragma unroll
        for (int ni = 0; ni < 4; ni++)
#pragma unroll
            for (int r = 0; r < 4; r++) c[mi][ni][r] = 0.f;

    const int NT = K / BK;

    // prologue: fill buffer 0 (tile 0)
    {
        CPA16(dAh, Agh);
        CPA16(dAl, Agl);
        CPA16(dBh, Bgh);
        CPA16(dBl, Bgl);
        CP_COMMIT();
    }

    for (int t = 0; t < NT; t++) {
        const int buf = t & 1;
        if (t + 1 < NT) {
            const int nb = buf ^ 1;
            CPA16(dAh + nb * A_BUF, Agh + (t + 1) * BK);
            CPA16(dAl + nb * A_BUF, Agl + (t + 1) * BK);
            CPA16(dBh + nb * B_BUF, Bgh + (size_t)(t + 1) * BK * N);
            CPA16(dBl + nb * B_BUF, Bgl + (size_t)(t + 1) * BK * N);
            CP_COMMIT();
            CP_WAIT1();
        } else {
            CP_WAIT0();
        }
        __syncthreads();

        // fragment loads
        uint32_t a_h[4][4], a_l[4][4], b_h[4][2], b_l[4][2];
        const uint32_t ab = aAddr0 + buf * A_BUF;
        const uint32_t bb = bAddr0 + buf * B_BUF;
#pragma unroll
        for (int mi = 0; mi < 4; mi++) {
            ldsm4(a_h[mi], ab + mi * (16 * A_PAD * 2));
            ldsm4(a_l[mi], ab + A_HL + mi * (16 * A_PAD * 2));
        }
#pragma unroll
        for (int ni = 0; ni < 4; ni++) {
            ldsm2t(b_h[ni], bb + ni * 16);
            ldsm2t(b_l[ni], bb + B_HL + ni * 16);
        }

        // 3 split terms; same accumulator touched once per 16 mmas
#pragma unroll
        for (int mi = 0; mi < 4; mi++)
#pragma unroll
            for (int ni = 0; ni < 4; ni++)
                mma16816(c[mi][ni], a_h[mi], b_h[ni]);
#pragma unroll
        for (int mi = 0; mi < 4; mi++)
#pragma unroll
            for (int ni = 0; ni < 4; ni++)
                mma16816(c[mi][ni], a_h[mi], b_l[ni]);
#pragma unroll
        for (int mi = 0; mi < 4; mi++)
#pragma unroll
            for (int ni = 0; ni < 4; ni++)
                mma16816(c[mi][ni], a_l[mi], b_h[ni]);

        __syncthreads();
    }

    // Epilogue: bias (+ phi), direct global stores
    const int crow0 = bm * BM + warpM * 64 + (lane >> 2);
    const int ccol0 = bn * BN + warpN * 32 + (lane & 3) * 2;
#pragma unroll
    for (int ni = 0; ni < 4; ni++) {
        const int col = ccol0 + ni * 8;
        const float b0 = bias[col];
        const float b1 = bias[col + 1];
#pragma unroll
        for (int mi = 0; mi < 4; mi++) {
            const int row = crow0 + mi * 16;
            float v0 = c[mi][ni][0] + b0;
            float v1 = c[mi][ni][1] + b1;
            float v2 = c[mi][ni][2] + b0;
            float v3 = c[mi][ni][3] + b1;
            if (ACT) {
                v0 = (v0 > 0.f) ? (v0 + 1.f) : expf(v0);
                v1 = (v1 > 0.f) ? (v1 + 1.f) : expf(v1);
                v2 = (v2 > 0.f) ? (v2 + 1.f) : expf(v2);
                v3 = (v3 > 0.f) ? (v3 + 1.f) : expf(v3);
            }
            float2 p0 = make_float2(v0, v1);
            float2 p1 = make_float2(v2, v3);
            *(float2*)(C + (size_t)row * N + col)       = p0;
            *(float2*)(C + (size_t)(row + 8) * N + col) = p1;
        }
    }
}

// ---------------------------------------------------------------------------
// KV state: per (b,h): kv[d][e] = sum_n kf[n,d] * v[n,e]; ksum[d] = sum_n kf[n,d]
// ---------------------------------------------------------------------------
__global__ __launch_bounds__(256) void kv_state_kernel(
    const float* __restrict__ Kf, const float* __restrict__ V)
{
    const int bh = blockIdx.x;
    const int b = bh >> 4;
    const int h = bh & 15;

    __shared__ float ks[64][64];
    __shared__ float vs[64][64];

    const int tid = threadIdx.x;
    const int d0 = (tid >> 4) * 4;
    const int e0 = (tid & 15) * 4;

    const int lrow = tid >> 2;
    const int lc0  = (tid & 3) * 16;

    const float* kb = Kf + (size_t)(b * SEQ) * DM + h * DK;
    const float* vb = V  + (size_t)(b * SEQ) * DM + h * DK;

    float acc[4][4];
#pragma unroll
    for (int i = 0; i < 4; i++)
#pragma unroll
        for (int j = 0; j < 4; j++) acc[i][j] = 0.f;
    float ksacc = 0.f;

    for (int c = 0; c < SEQ; c += 64) {
        const float* kr = kb + (size_t)(c + lrow) * DM;
        const float* vr = vb + (size_t)(c + lrow) * DM;
#pragma unroll
        for (int j = 0; j < 4; j++) {
            *(float4*)&ks[lrow][lc0 + j * 4] = *(const float4*)(kr + lc0 + j * 4);
            *(float4*)&vs[lrow][lc0 + j * 4] = *(const float4*)(vr + lc0 + j * 4);
        }
        __syncthreads();

#pragma unroll 8
        for (int n = 0; n < 64; n++) {
            float a[4], bb[4];
            *(float4*)a  = *(float4*)&ks[n][d0];
            *(float4*)bb = *(float4*)&vs[n][e0];
#pragma unroll
            for (int i = 0; i < 4; i++)
#pragma unroll
                for (int j = 0; j < 4; j++)
                    acc[i][j] = fmaf(a[i], bb[j], acc[i][j]);
        }

        if (tid < 64) {
#pragma unroll 8
            for (int n = 0; n < 64; n++) ksacc += ks[n][tid];
        }
        __syncthreads();
    }

    float* kvout = g_kv + (size_t)bh * DK * DK;
#pragma unroll
    for (int i = 0; i < 4; i++)
        *(float4*)(kvout + (size_t)(d0 + i) * DK + e0) = *(float4*)acc[i];

    if (tid < 64) g_ksum[bh * DK + tid] = ksacc;
}

// ---------------------------------------------------------------------------
// Attention out: out[n,e] = (qf[n,:].kv[:,e]) / (qf[n,:].ksum + eps)
// ---------------------------------------------------------------------------
__global__ __launch_bounds__(256) void attn_out_kernel(const float* __restrict__ Qf)
{
    const int bh = blockIdx.x;
    const int b = bh >> 4;
    const int h = bh & 15;

    __shared__ float kvs[64][64];
    __shared__ float ksum_s[64];
    __shared__ float qs[64][65];
    __shared__ float denom[64];

    const int tid = threadIdx.x;
    const int lrow = tid >> 2;
    const int lc0  = (tid & 3) * 16;

    {
        const float* kvb = g_kv + (size_t)bh * DK * DK;
#pragma unroll
        for (int j = 0; j < 4; j++)
            *(float4*)&kvs[lrow][lc0 + j * 4] = *(const float4*)(kvb + (size_t)lrow * DK + lc0 + j * 4);
        if (tid < 64) ksum_s[tid] = g_ksum[bh * DK + tid];
    }
    __syncthreads();

    const float* qb = Qf     + (size_t)(b * SEQ) * DM + h * DK;
    float*       ob = g_attn + (size_t)(b * SEQ) * DM + h * DK;

    const int n0 = (tid >> 4) * 4;
    const int e0 = (tid & 15) * 4;

    for (int c = 0; c < SEQ; c += 64) {
        const float* qr = qb + (size_t)(c + lrow) * DM;
#pragma unroll
        for (int j = 0; j < 4; j++) {
            float4 t = *(const float4*)(qr + lc0 + j * 4);
            qs[lrow][lc0 + j * 4 + 0] = t.x;
            qs[lrow][lc0 + j * 4 + 1] = t.y;
            qs[lrow][lc0 + j * 4 + 2] = t.z;
            qs[lrow][lc0 + j * 4 + 3] = t.w;
        }
        __syncthreads();

        if (tid < 64) {
            float s = 0.f;
#pragma unroll 8
            for (int d = 0; d < 64; d++) s = fmaf(qs[tid][d], ksum_s[d], s);
            denom[tid] = s + 1e-6f;
        }
        __syncthreads();

        float acc[4][4];
#pragma unroll
        for (int i = 0; i < 4; i++)
#pragma unroll
            for (int j = 0; j < 4; j++) acc[i][j] = 0.f;

#pragma unroll 8
        for (int d = 0; d < 64; d++) {
            float a[4], bb[4];
#pragma unroll
            for (int i = 0; i < 4; i++) a[i] = qs[n0 + i][d];
            *(float4*)bb = *(float4*)&kvs[d][e0];
#pragma unroll
            for (int i = 0; i < 4; i++)
#pragma unroll
                for (int j = 0; j < 4; j++)
                    acc[i][j] = fmaf(a[i], bb[j], acc[i][j]);
        }

#pragma unroll
        for (int i = 0; i < 4; i++) {
            float inv = 1.f / denom[n0 + i];
            float row[4];
#pragma unroll
            for (int j = 0; j < 4; j++) row[j] = acc[i][j] * inv;
            *(float4*)(ob + (size_t)(c + n0 + i) * DM + e0) = *(float4*)row;
        }
        __syncthreads();
    }
}

// ---------------------------------------------------------------------------
extern "C" void kernel_launch(void* const* d_in, const int* in_sizes, int n_in,
                              void* d_out, int out_size)
{
    const float* x  = (const float*)d_in[0];
    const float* Wq = (const float*)d_in[1];
    const float* bq = (const float*)d_in[2];
    const float* Wk = (const float*)d_in[3];
    const float* bk = (const float*)d_in[4];
    const float* Wv = (const float*)d_in[5];
    const float* bv = (const float*)d_in[6];
    const float* Wo = (const float*)d_in[7];
    const float* bo = (const float*)d_in[8];
    float* out = (float*)d_out;

    float *q, *k, *v, *attn;
    cudaGetSymbolAddress((void**)&q,    g_q);
    cudaGetSymbolAddress((void**)&k,    g_k);
    cudaGetSymbolAddress((void**)&v,    g_v);
    cudaGetSymbolAddress((void**)&attn, g_attn);

    __nv_bfloat16 *xh, *xl, *ath, *atl, *wh, *wl;
    cudaGetSymbolAddress((void**)&xh,  g_xh);
    cudaGetSymbolAddress((void**)&xl,  g_xl);
    cudaGetSymbolAddress((void**)&ath, g_ath);
    cudaGetSymbolAddress((void**)&atl, g_atl);
    cudaGetSymbolAddress((void**)&wh,  g_wh);
    cudaGetSymbolAddress((void**)&wl,  g_wl);

    const int nx = MTOT * DM;        // 16.7M
    const int nw = DM * DM;          // 1M

    split_kernel<<<nx / 1024, 256>>>(x,  xh, xl, nx);
    split_kernel<<<nw / 1024, 256>>>(Wq, wh + 0 * nw, wl + 0 * nw, nw);
    split_kernel<<<nw / 1024, 256>>>(Wk, wh + 1 * nw, wl + 1 * nw, nw);
    split_kernel<<<nw / 1024, 256>>>(Wv, wh + 2 * nw, wl + 2 * nw, nw);
    split_kernel<<<nw / 1024, 256>>>(Wo, wh + 3 * nw, wl + 3 * nw, nw);

    dim3 gg(DM / BN, MTOT / BM);     // (8, 128)

    mma_gemm<1><<<gg, 256>>>(xh, xl, wh + 0 * nw, wl + 0 * nw, bq, q, MTOT, DM, DM);
    mma_gemm<1><<<gg, 256>>>(xh, xl, wh + 1 * nw, wl + 1 * nw, bk, k, MTOT, DM, DM);
    mma_gemm<0><<<gg, 256>>>(xh, xl, wh + 2 * nw, wl + 2 * nw, bv, v, MTOT, DM, DM);

    kv_state_kernel<<<BATCH * NH, 256>>>(k, v);
    attn_out_kernel<<<BATCH * NH, 256>>>(q);

    split_kernel<<<nx / 1024, 256>>>(attn, ath, atl, nx);
    mma_gemm<0><<<gg, 256>>>(ath, atl, wh + 3 * nw, wl + 3 * nw, bo, out, MTOT, DM, DM);
}